// round 2
// baseline (speedup 1.0000x reference)
#include <cuda_runtime.h>
#include <cstdint>

// Problem dims (fixed by the dataset)
#define B_  1024
#define S_  64
#define R_  1024
#define E_  1024
#define CD_ 1024
#define ED_ 1024
#define H_  512

// ---------------- scratch (static __device__, no allocs) ----------------
__device__ float g_xcat0[(size_t)B_ * (E_ + ED_)];      // [B, 2048]  xt|event
__device__ float g_xcat1[(size_t)B_ * (E_ + CD_)];      // [B, 2048]  xt|att
__device__ float g_gates0[(size_t)B_ * 4 * R_];         // [B, 4096]
__device__ float g_gates1[(size_t)B_ * 4 * R_];         // [B, 4096]
__device__ float g_atth[(size_t)B_ * H_];               // [B, 512]
__device__ float g_att[(size_t)B_ * S_ * H_];           // [B*S, 512]
__device__ float g_scores[(size_t)B_ * S_];             // [B, S]
__device__ float g_wts[(size_t)B_ * S_];                // [B, S]
__device__ float g_attout[(size_t)B_ * CD_];            // [B, 1024]

// ---------------- GEMM: C[M,N] = A[M,K] @ W[N,K]^T (+bias | accumulate) ----------------
// NT layout: both operands K-contiguous. 128x128x8 tile, 256 threads, 8x8/thread.
// Software-pipelined: next k-tile prefetched into registers during compute.
#define BM 128
#define BN 128
#define BK 8

__global__ __launch_bounds__(256, 2)
void gemm_nt(const float* __restrict__ A, const float* __restrict__ W,
             const float* __restrict__ b1, const float* __restrict__ b2,
             float* __restrict__ C, int M, int N, int K, int accumulate)
{
    __shared__ __align__(16) float As[BK][BM];
    __shared__ __align__(16) float Bs[BK][BN];

    const int t  = threadIdx.x;
    const int tx = t & 15;          // column group 0..15
    const int ty = t >> 4;          // row group 0..15
    const long bm = (long)blockIdx.y * BM;
    const long bn = (long)blockIdx.x * BN;

    // global tile loaders: each thread loads one float4 of A and one of W per k-tile
    const int lm  = t >> 1;         // 0..127
    const int lk4 = (t & 1) * 4;    // 0 or 4
    const float* Ag = A + (bm + lm) * (long)K + lk4;
    const float* Wg = W + (bn + lm) * (long)K + lk4;

    float acc[8][8];
#pragma unroll
    for (int i = 0; i < 8; i++)
#pragma unroll
        for (int j = 0; j < 8; j++) acc[i][j] = 0.f;

    // prologue: prefetch first tile
    float4 av = *(const float4*)(Ag);
    float4 wv = *(const float4*)(Wg);

    for (int k0 = 0; k0 < K; k0 += BK) {
        As[lk4 + 0][lm] = av.x; As[lk4 + 1][lm] = av.y;
        As[lk4 + 2][lm] = av.z; As[lk4 + 3][lm] = av.w;
        Bs[lk4 + 0][lm] = wv.x; Bs[lk4 + 1][lm] = wv.y;
        Bs[lk4 + 2][lm] = wv.z; Bs[lk4 + 3][lm] = wv.w;
        __syncthreads();

        // prefetch next tile into registers while computing on SMEM tile
        if (k0 + BK < K) {
            av = *(const float4*)(Ag + k0 + BK);
            wv = *(const float4*)(Wg + k0 + BK);
        }

#pragma unroll
        for (int kk = 0; kk < BK; kk++) {
            float4 a0 = *(const float4*)&As[kk][ty * 4];
            float4 a1 = *(const float4*)&As[kk][64 + ty * 4];
            float4 v0 = *(const float4*)&Bs[kk][tx * 4];
            float4 v1 = *(const float4*)&Bs[kk][64 + tx * 4];
            float a[8] = {a0.x, a0.y, a0.z, a0.w, a1.x, a1.y, a1.z, a1.w};
            float b[8] = {v0.x, v0.y, v0.z, v0.w, v1.x, v1.y, v1.z, v1.w};
#pragma unroll
            for (int i = 0; i < 8; i++)
#pragma unroll
                for (int j = 0; j < 8; j++)
                    acc[i][j] = fmaf(a[i], b[j], acc[i][j]);
        }
        __syncthreads();
    }

    // epilogue
    const long col0 = bn + tx * 4;
    const long col1 = bn + 64 + tx * 4;
    float4 bb0 = make_float4(0.f, 0.f, 0.f, 0.f);
    float4 bb1 = make_float4(0.f, 0.f, 0.f, 0.f);
    if (!accumulate) {
        if (b1) {
            float4 u = *(const float4*)(b1 + col0);
            float4 v = *(const float4*)(b1 + col1);
            bb0.x += u.x; bb0.y += u.y; bb0.z += u.z; bb0.w += u.w;
            bb1.x += v.x; bb1.y += v.y; bb1.z += v.z; bb1.w += v.w;
        }
        if (b2) {
            float4 u = *(const float4*)(b2 + col0);
            float4 v = *(const float4*)(b2 + col1);
            bb0.x += u.x; bb0.y += u.y; bb0.z += u.z; bb0.w += u.w;
            bb1.x += v.x; bb1.y += v.y; bb1.z += v.z; bb1.w += v.w;
        }
    }
#pragma unroll
    for (int i = 0; i < 8; i++) {
        long row = bm + ((i < 4) ? (ty * 4 + i) : (64 + ty * 4 + (i - 4)));
        float4 o0 = make_float4(acc[i][0], acc[i][1], acc[i][2], acc[i][3]);
        float4 o1 = make_float4(acc[i][4], acc[i][5], acc[i][6], acc[i][7]);
        float4* p0 = (float4*)(C + row * N + col0);
        float4* p1 = (float4*)(C + row * N + col1);
        if (accumulate) {
            float4 c0 = *p0, c1 = *p1;
            o0.x += c0.x; o0.y += c0.y; o0.z += c0.z; o0.w += c0.w;
            o1.x += c1.x; o1.y += c1.y; o1.z += c1.z; o1.w += c1.w;
        } else {
            o0.x += bb0.x; o0.y += bb0.y; o0.z += bb0.z; o0.w += bb0.w;
            o1.x += bb1.x; o1.y += bb1.y; o1.z += bb1.z; o1.w += bb1.w;
        }
        *p0 = o0; *p1 = o1;
    }
}

// ---------------- concat rows: out[b] = [a_row | b_row] (widths in float4s) ----------------
__global__ void concat2_kernel(const float4* __restrict__ a, const float4* __restrict__ b,
                               float4* __restrict__ out, int wa4, int wb4)
{
    long i = (long)blockIdx.x * blockDim.x + threadIdx.x;
    int w = wa4 + wb4;
    long total = (long)B_ * w;
    if (i >= total) return;
    long row = i / w;
    int c = (int)(i - row * w);
    out[i] = (c < wa4) ? a[row * wa4 + c] : b[row * wb4 + (c - wa4)];
}

// ---------------- scores[b,s] = sum_h tanh(att[b,s,h]+atth[b,h]) * Wa[h] + ba ----------------
__global__ void scores_kernel(const float* __restrict__ att, const float* __restrict__ atth,
                              const float* __restrict__ Wa, const float* __restrict__ ba,
                              float* __restrict__ scores)
{
    int row  = blockIdx.x * 8 + (threadIdx.x >> 5);  // b*S + s
    int lane = threadIdx.x & 31;
    int b = row >> 6;                                 // /S_
    const float4* ar = (const float4*)(att + (long)row * H_);
    const float4* hr = (const float4*)(atth + (long)b * H_);
    const float4* wa = (const float4*)Wa;
    float sum = 0.f;
#pragma unroll
    for (int h = lane; h < H_ / 4; h += 32) {
        float4 av = ar[h], hv = hr[h], wv = wa[h];
        sum += tanhf(av.x + hv.x) * wv.x + tanhf(av.y + hv.y) * wv.y
             + tanhf(av.z + hv.z) * wv.z + tanhf(av.w + hv.w) * wv.w;
    }
#pragma unroll
    for (int o = 16; o > 0; o >>= 1) sum += __shfl_xor_sync(0xffffffffu, sum, o);
    if (lane == 0) scores[row] = sum + ba[0];
}

// ---------------- masked softmax over S (one warp per b) ----------------
__global__ void softmax_kernel(const float* __restrict__ scores, const int* __restrict__ mask,
                               float* __restrict__ wts)
{
    int b = blockIdx.x;
    int lane = threadIdx.x;           // 32 threads
    float x0 = scores[b * S_ + lane];
    float x1 = scores[b * S_ + lane + 32];
    float mx = fmaxf(x0, x1);
#pragma unroll
    for (int o = 16; o > 0; o >>= 1) mx = fmaxf(mx, __shfl_xor_sync(0xffffffffu, mx, o));
    float m0 = (float)mask[b * S_ + lane];
    float m1 = (float)mask[b * S_ + lane + 32];
    float n0 = expf(x0 - mx) * m0;
    float n1 = expf(x1 - mx) * m1;
    float z = n0 + n1;
#pragma unroll
    for (int o = 16; o > 0; o >>= 1) z += __shfl_xor_sync(0xffffffffu, z, o);
    float inv = 1.f / z;
    wts[b * S_ + lane]      = n0 * inv;
    wts[b * S_ + lane + 32] = n1 * inv;
}

// ---------------- attout[b,d] = sum_s wts[b,s] * clip[b,s,d] ----------------
__global__ void attsum_kernel(const float* __restrict__ clip, const float* __restrict__ wts,
                              float* __restrict__ attout)
{
    int b = blockIdx.x;
    int t = threadIdx.x;              // 256 threads; d4 = t
    __shared__ float w[S_];
    if (t < S_) w[t] = wts[b * S_ + t];
    __syncthreads();
    const float4* cb = (const float4*)(clip + (long)b * S_ * CD_);
    float4 acc = make_float4(0.f, 0.f, 0.f, 0.f);
#pragma unroll 8
    for (int s = 0; s < S_; s++) {
        float ws = w[s];
        float4 v = cb[s * (CD_ / 4) + t];
        acc.x = fmaf(ws, v.x, acc.x);
        acc.y = fmaf(ws, v.y, acc.y);
        acc.z = fmaf(ws, v.z, acc.z);
        acc.w = fmaf(ws, v.w, acc.w);
    }
    ((float4*)attout)[(long)b * (CD_ / 4) + t] = acc;
}

// ---------------- LSTM pointwise ----------------
__device__ __forceinline__ float sigm(float x) { return 1.f / (1.f + expf(-x)); }

__global__ void lstm_act(const float* __restrict__ gates, const float* __restrict__ cprev,
                         float* __restrict__ out_half,   // d_out + stream*R_, row stride 2R
                         float* __restrict__ nh, float* __restrict__ nc)
{
    long i = (long)blockIdx.x * blockDim.x + threadIdx.x;
    if (i >= (long)B_ * R_) return;
    long b = i >> 10;
    int r = (int)(i & (R_ - 1));
    const float* g = gates + b * (4 * R_);
    float iv = sigm(g[r]);
    float fv = sigm(g[R_ + r]);
    float gv = tanhf(g[2 * R_ + r]);
    float ov = sigm(g[3 * R_ + r]);
    float c = fv * cprev[i] + iv * gv;
    float h = ov * tanhf(c);
    out_half[b * (2 * R_) + r] = h;
    nh[i] = h;
    nc[i] = c;
}

// ---------------- launch ----------------
extern "C" void kernel_launch(void* const* d_in, const int* in_sizes, int n_in,
                              void* d_out, int out_size)
{
    (void)in_sizes; (void)n_in; (void)out_size;
    const float* xt      = (const float*)d_in[0];
    // d_in[1] = video (unused)
    const float* event   = (const float*)d_in[2];
    const float* clip    = (const float*)d_in[3];
    const int*   clip_mask = (const int*)d_in[4];
    const float* state_h = (const float*)d_in[5];
    const float* state_c = (const float*)d_in[6];
    const float* W_ih0   = (const float*)d_in[7];
    const float* b_ih0   = (const float*)d_in[8];
    const float* W_hh0   = (const float*)d_in[9];
    const float* b_hh0   = (const float*)d_in[10];
    const float* W_ih1   = (const float*)d_in[11];
    const float* b_ih1   = (const float*)d_in[12];
    const float* W_hh1   = (const float*)d_in[13];
    const float* b_hh1   = (const float*)d_in[14];
    const float* W_ctx   = (const float*)d_in[15];
    const float* b_ctx   = (const float*)d_in[16];
    const float* W_h2a   = (const float*)d_in[17];
    const float* b_h2a   = (const float*)d_in[18];
    const float* W_alpha = (const float*)d_in[19];
    const float* b_alpha = (const float*)d_in[20];

    float* out   = (float*)d_out;                 // [B, 2R]
    float* newh  = out + (long)B_ * 2 * R_;       // [2, B, R]
    float* newc  = newh + 2L * B_ * R_;           // [2, B, R]

    float *xcat0, *xcat1, *gates0, *gates1, *atth, *att, *scores, *wts, *attout;
    cudaGetSymbolAddress((void**)&xcat0,  g_xcat0);
    cudaGetSymbolAddress((void**)&xcat1,  g_xcat1);
    cudaGetSymbolAddress((void**)&gates0, g_gates0);
    cudaGetSymbolAddress((void**)&gates1, g_gates1);
    cudaGetSymbolAddress((void**)&atth,   g_atth);
    cudaGetSymbolAddress((void**)&att,    g_att);
    cudaGetSymbolAddress((void**)&scores, g_scores);
    cudaGetSymbolAddress((void**)&wts,    g_wts);
    cudaGetSymbolAddress((void**)&attout, g_attout);

    const float* h0 = state_h;                    // state_h[0]
    const float* h1 = state_h + (long)B_ * R_;    // state_h[1] (= pre_h1)
    const float* c0 = state_c;
    const float* c1 = state_c + (long)B_ * R_;

    // 1) xcat0 = [xt | event]
    {
        long total = (long)B_ * 512;              // float4 count (2048 floats/row)
        concat2_kernel<<<(int)((total + 255) / 256), 256>>>(
            (const float4*)xt, (const float4*)event, (float4*)xcat0, 256, 256);
    }
    // 2) gates0 = xcat0 @ W_ih0^T + b_ih0 + b_hh0
    gemm_nt<<<dim3(4 * R_ / BN, B_ / BM), 256>>>(xcat0, W_ih0, b_ih0, b_hh0,
                                                 gates0, B_, 4 * R_, E_ + ED_, 0);
    // 3) gates0 += h0 @ W_hh0^T
    gemm_nt<<<dim3(4 * R_ / BN, B_ / BM), 256>>>(h0, W_hh0, nullptr, nullptr,
                                                 gates0, B_, 4 * R_, R_, 1);
    // 4) atth = h1 @ W_h2a^T + b_h2a
    gemm_nt<<<dim3(H_ / BN, B_ / BM), 256>>>(h1, W_h2a, b_h2a, nullptr,
                                             atth, B_, H_, R_, 0);
    // 5) att = clip2d @ W_ctx^T + b_ctx   [65536, 512]
    gemm_nt<<<dim3(H_ / BN, (B_ * S_) / BM), 256>>>(clip, W_ctx, b_ctx, nullptr,
                                                    att, B_ * S_, H_, CD_, 0);
    // 6) scores
    scores_kernel<<<(B_ * S_) / 8, 256>>>(att, atth, W_alpha, b_alpha, scores);
    // 7) masked softmax + renorm
    softmax_kernel<<<B_, 32>>>(scores, clip_mask, wts);
    // 8) attout = weights @ clip
    attsum_kernel<<<B_, 256>>>(clip, wts, attout);
    // 9) xcat1 = [xt | attout]
    {
        long total = (long)B_ * 512;
        concat2_kernel<<<(int)((total + 255) / 256), 256>>>(
            (const float4*)xt, (const float4*)attout, (float4*)xcat1, 256, 256);
    }
    // 10) gates1 = xcat1 @ W_ih1^T + b_ih1 + b_hh1
    gemm_nt<<<dim3(4 * R_ / BN, B_ / BM), 256>>>(xcat1, W_ih1, b_ih1, b_hh1,
                                                 gates1, B_, 4 * R_, E_ + CD_, 0);
    // 11) gates1 += h1 @ W_hh1^T
    gemm_nt<<<dim3(4 * R_ / BN, B_ / BM), 256>>>(h1, W_hh1, nullptr, nullptr,
                                                 gates1, B_, 4 * R_, R_, 1);
    // 12/13) LSTM pointwise for both streams (writes output concat + new_h + new_c)
    {
        int threads = 256;
        int blocks = (int)(((long)B_ * R_ + threads - 1) / threads);
        lstm_act<<<blocks, threads>>>(gates0, c0, out,       newh,                 newc);
        lstm_act<<<blocks, threads>>>(gates1, c1, out + R_,  newh + (long)B_ * R_, newc + (long)B_ * R_);
    }
}

// round 6
// speedup vs baseline: 2.0085x; 2.0085x over previous
#include <cuda_runtime.h>
#include <cuda_bf16.h>
#include <cuda_fp16.h>
#include <cstdint>
#include <cstring>

// Problem dims (fixed)
#define B_  1024
#define S_  64
#define R_  1024
#define H_  512
#define BS_ (B_ * S_)     // 65536

#define AST 80            // smem row stride bytes: 32 elems * 2B + 16B pad (conflict-free)

// ---------------------------------------------------------------------------
// scratch
// ---------------------------------------------------------------------------
__device__ float g_gates0[(size_t)B_ * 4 * R_];
__device__ float g_gates1[(size_t)B_ * 4 * R_];
__device__ float g_atth[(size_t)B_ * H_];
__device__ float g_scores4[(size_t)4 * BS_];
__device__ float g_wts[(size_t)B_ * S_];
__device__ float g_attout[(size_t)B_ * R_];

// ---------------------------------------------------------------------------
// PTX wrappers (baseline ISA only: ldmatrix + mma.sync, sm_80+)
// ---------------------------------------------------------------------------
__device__ __forceinline__ uint32_t smem_u32(const void* p) {
    uint32_t a;
    asm("{ .reg .u64 t; cvta.to.shared.u64 t, %1; cvt.u32.u64 %0, t; }" : "=r"(a) : "l"(p));
    return a;
}
__device__ __forceinline__ void ldsm_x4(uint32_t* r, uint32_t addr) {
    asm volatile("ldmatrix.sync.aligned.m8n8.x4.shared.b16 {%0,%1,%2,%3}, [%4];"
                 : "=r"(r[0]), "=r"(r[1]), "=r"(r[2]), "=r"(r[3]) : "r"(addr));
}
__device__ __forceinline__ void mma_bf16(float* d, const uint32_t* a, const uint32_t* b) {
    asm volatile("mma.sync.aligned.m16n8k16.row.col.f32.bf16.bf16.f32 "
                 "{%0,%1,%2,%3}, {%4,%5,%6,%7}, {%8,%9}, {%0,%1,%2,%3};"
                 : "+f"(d[0]), "+f"(d[1]), "+f"(d[2]), "+f"(d[3])
                 : "r"(a[0]), "r"(a[1]), "r"(a[2]), "r"(a[3]), "r"(b[0]), "r"(b[1]));
}
__device__ __forceinline__ void mma_f16(float* d, const uint32_t* a, const uint32_t* b) {
    asm volatile("mma.sync.aligned.m16n8k16.row.col.f32.f16.f16.f32 "
                 "{%0,%1,%2,%3}, {%4,%5,%6,%7}, {%8,%9}, {%0,%1,%2,%3};"
                 : "+f"(d[0]), "+f"(d[1]), "+f"(d[2]), "+f"(d[3])
                 : "r"(a[0]), "r"(a[1]), "r"(a[2]), "r"(a[3]), "r"(b[0]), "r"(b[1]));
}
__device__ __forceinline__ uint32_t bf2u(__nv_bfloat162 h) { uint32_t u; memcpy(&u, &h, 4); return u; }
__device__ __forceinline__ uint32_t hf2u(__half2 h)        { uint32_t u; memcpy(&u, &h, 4); return u; }

// Convert 16 fp32 (4 float4) -> 16 bf16 hi + 16 bf16 lo, store 2x uint4 each.
__device__ __forceinline__ void cvt_store_bf16_split(const float4* v, char* dsthi, char* dstlo) {
    uint32_t h[8], l[8];
#pragma unroll
    for (int i = 0; i < 4; i++) {
        float2 xy = make_float2(v[i].x, v[i].y), zw = make_float2(v[i].z, v[i].w);
        __nv_bfloat162 hxy = __float22bfloat162_rn(xy), hzw = __float22bfloat162_rn(zw);
        float2 bxy = __bfloat1622float2(hxy), bzw = __bfloat1622float2(hzw);
        __nv_bfloat162 lxy = __float22bfloat162_rn(make_float2(xy.x - bxy.x, xy.y - bxy.y));
        __nv_bfloat162 lzw = __float22bfloat162_rn(make_float2(zw.x - bzw.x, zw.y - bzw.y));
        h[2*i] = bf2u(hxy); h[2*i+1] = bf2u(hzw);
        l[2*i] = bf2u(lxy); l[2*i+1] = bf2u(lzw);
    }
    ((uint4*)dsthi)[0] = make_uint4(h[0], h[1], h[2], h[3]);
    ((uint4*)dsthi)[1] = make_uint4(h[4], h[5], h[6], h[7]);
    ((uint4*)dstlo)[0] = make_uint4(l[0], l[1], l[2], l[3]);
    ((uint4*)dstlo)[1] = make_uint4(l[4], l[5], l[6], l[7]);
}
// Convert 16 fp32 -> 16 fp16, store 2x uint4.
__device__ __forceinline__ void cvt_store_f16(const float4* v, char* dst) {
    uint32_t h[8];
#pragma unroll
    for (int i = 0; i < 4; i++) {
        h[2*i]   = hf2u(__float22half2_rn(make_float2(v[i].x, v[i].y)));
        h[2*i+1] = hf2u(__float22half2_rn(make_float2(v[i].z, v[i].w)));
    }
    ((uint4*)dst)[0] = make_uint4(h[0], h[1], h[2], h[3]);
    ((uint4*)dst)[1] = make_uint4(h[4], h[5], h[6], h[7]);
}

// ---------------------------------------------------------------------------
// Split-bf16 3-term GEMM: C[M,N] = A @ W^T (+b1 +b2), fp32 in/out.
// A: up to 3 segments of width 1024; W: 2 segments widths WK1, WK2.
// CTA tile 128x128, 256 threads, warp tile 64x32, K-chunk 32.
// ---------------------------------------------------------------------------
__global__ __launch_bounds__(256, 1)
void mma_gemm_split(const float* __restrict__ A0, const float* __restrict__ A1,
                    const float* __restrict__ A2,
                    const float* __restrict__ W0, const float* __restrict__ W1,
                    int WK1, int WK2, int K,
                    const float* __restrict__ b1, const float* __restrict__ b2,
                    float* __restrict__ C, int N)
{
    __shared__ __align__(16) char smAhi[128 * AST];
    __shared__ __align__(16) char smAlo[128 * AST];
    __shared__ __align__(16) char smWhi[128 * AST];
    __shared__ __align__(16) char smWlo[128 * AST];
    const uint32_t sbAhi = smem_u32(smAhi), sbAlo = smem_u32(smAlo);
    const uint32_t sbWhi = smem_u32(smWhi), sbWlo = smem_u32(smWlo);

    const int t = threadIdx.x, lane = t & 31, wid = t >> 5;
    const int wm = wid >> 2, wn = wid & 3;          // 2 x 4 warps
    const long bm = (long)blockIdx.y * 128;
    const long bn = (long)blockIdx.x * 128;
    const float* Aseg[3] = {A0, A1, A2};

    const int lr = t >> 1;       // load row 0..127
    const int lh = t & 1;        // 16-float half

    float acc[4][4][4];
#pragma unroll
    for (int i = 0; i < 4; i++)
#pragma unroll
        for (int j = 0; j < 4; j++)
#pragma unroll
            for (int k = 0; k < 4; k++) acc[i][j][k] = 0.f;

    float4 pa[4], pw[4];
    // prefetch chunk 0
    {
        const float4* ap = (const float4*)(Aseg[0] + (bm + lr) * 1024L + lh * 16);
        const float4* wp = (const float4*)(W0 + (bn + lr) * (long)WK1 + lh * 16);
#pragma unroll
        for (int i = 0; i < 4; i++) { pa[i] = ap[i]; pw[i] = wp[i]; }
    }

    const int NC = K >> 5;
    for (int c = 0; c < NC; c++) {
        cvt_store_bf16_split(pa, smAhi + lr * AST + lh * 32, smAlo + lr * AST + lh * 32);
        cvt_store_bf16_split(pw, smWhi + lr * AST + lh * 32, smWlo + lr * AST + lh * 32);
        __syncthreads();
        if (c + 1 < NC) {
            const int k0 = (c + 1) << 5;
            const float4* ap = (const float4*)(Aseg[k0 >> 10] + (bm + lr) * 1024L + (k0 & 1023) + lh * 16);
            const float* wbase = (k0 < WK1) ? (W0 + (bn + lr) * (long)WK1 + k0)
                                            : (W1 + (bn + lr) * (long)WK2 + (k0 - WK1));
            const float4* wp = (const float4*)(wbase + lh * 16);
#pragma unroll
            for (int i = 0; i < 4; i++) { pa[i] = ap[i]; pw[i] = wp[i]; }
        }
#pragma unroll
        for (int ks = 0; ks < 2; ks++) {
            const uint32_t kb = ks * 32 + ((lane >> 4) << 4);
            const int rl = lane & 15;
            uint32_t ahi[4][4], alo[4][4], bhi[2][4], blo[2][4];
#pragma unroll
            for (int mi = 0; mi < 4; mi++) {
                uint32_t off = (wm * 64 + mi * 16 + rl) * AST + kb;
                ldsm_x4(ahi[mi], sbAhi + off);
                ldsm_x4(alo[mi], sbAlo + off);
            }
#pragma unroll
            for (int bi = 0; bi < 2; bi++) {
                uint32_t off = (wn * 32 + bi * 16 + rl) * AST + kb;
                ldsm_x4(bhi[bi], sbWhi + off);
                ldsm_x4(blo[bi], sbWlo + off);
            }
#pragma unroll
            for (int mi = 0; mi < 4; mi++)
#pragma unroll
            for (int ni = 0; ni < 4; ni++) {
                const int bi = ni >> 1, s = ni & 1;
                uint32_t bh[2] = {bhi[bi][s], bhi[bi][2 + s]};
                uint32_t bl[2] = {blo[bi][s], blo[bi][2 + s]};
                mma_bf16(acc[mi][ni], ahi[mi], bh);
                mma_bf16(acc[mi][ni], ahi[mi], bl);
                mma_bf16(acc[mi][ni], alo[mi], bh);
            }
        }
        __syncthreads();
    }

    // epilogue: += biases, write fp32
#pragma unroll
    for (int mi = 0; mi < 4; mi++) {
        const long r0 = bm + wm * 64 + mi * 16 + (lane >> 2);
#pragma unroll
        for (int ni = 0; ni < 4; ni++) {
            const long col = bn + wn * 32 + ni * 8 + ((lane & 3) << 1);
            float bb0 = (b1 ? b1[col] : 0.f) + (b2 ? b2[col] : 0.f);
            float bb1 = (b1 ? b1[col + 1] : 0.f) + (b2 ? b2[col + 1] : 0.f);
            *(float2*)(C + r0 * N + col) =
                make_float2(acc[mi][ni][0] + bb0, acc[mi][ni][1] + bb1);
            *(float2*)(C + (r0 + 8) * N + col) =
                make_float2(acc[mi][ni][2] + bb0, acc[mi][ni][3] + bb1);
        }
    }
}

// ---------------------------------------------------------------------------
// Attention GEMM, single-pass fp16 + fused score epilogue.
// scores_part[bx*BS + m] = sum_{h in tile} tanh(gemm[m,h] + atth[b,h]) * walpha[h]
// M=65536 (clip rows), N=512 (H), K=1024. CTA 128x128, grid (4, 512).
// ---------------------------------------------------------------------------
__global__ __launch_bounds__(256, 1)
void mma_att(const float* __restrict__ clip, const float* __restrict__ Wc,
             const float* __restrict__ atth, const float* __restrict__ walpha,
             float* __restrict__ scores_part)
{
    __shared__ __align__(16) char smA[128 * AST];
    __shared__ __align__(16) char smW[128 * AST];
    __shared__ float smAtth[2 * 128];
    __shared__ float smWal[128];
    __shared__ float sc[128];
    const uint32_t sbA = smem_u32(smA), sbW = smem_u32(smW);

    const int t = threadIdx.x, lane = t & 31, wid = t >> 5;
    const int wm = wid >> 2, wn = wid & 3;
    const long bm = (long)blockIdx.y * 128;
    const int bx = blockIdx.x;

    if (t < 128) {
        smWal[t]  = walpha[bx * 128 + t];
        smAtth[t] = atth[(size_t)(bm >> 6) * H_ + bx * 128 + t];
        sc[t] = 0.f;
    } else if (t < 256) {
        smAtth[t] = atth[(size_t)((bm >> 6) + 1) * H_ + bx * 128 + (t - 128)];
    }

    const int lr = t >> 1;
    const int lh = t & 1;

    float acc[4][4][4];
#pragma unroll
    for (int i = 0; i < 4; i++)
#pragma unroll
        for (int j = 0; j < 4; j++)
#pragma unroll
            for (int k = 0; k < 4; k++) acc[i][j][k] = 0.f;

    float4 pa[4], pw[4];
    {
        const float4* ap = (const float4*)(clip + (bm + lr) * 1024L + lh * 16);
        const float4* wp = (const float4*)(Wc + ((long)bx * 128 + lr) * 1024L + lh * 16);
#pragma unroll
        for (int i = 0; i < 4; i++) { pa[i] = ap[i]; pw[i] = wp[i]; }
    }

    const int NC = 1024 >> 5;   // 32
    for (int c = 0; c < NC; c++) {
        cvt_store_f16(pa, smA + lr * AST + lh * 32);
        cvt_store_f16(pw, smW + lr * AST + lh * 32);
        __syncthreads();
        if (c + 1 < NC) {
            const int k0 = (c + 1) << 5;
            const float4* ap = (const float4*)(clip + (bm + lr) * 1024L + k0 + lh * 16);
            const float4* wp = (const float4*)(Wc + ((long)bx * 128 + lr) * 1024L + k0 + lh * 16);
#pragma unroll
            for (int i = 0; i < 4; i++) { pa[i] = ap[i]; pw[i] = wp[i]; }
        }
#pragma unroll
        for (int ks = 0; ks < 2; ks++) {
            const uint32_t kb = ks * 32 + ((lane >> 4) << 4);
            const int rl = lane & 15;
            uint32_t af[4][4], bf[2][4];
#pragma unroll
            for (int mi = 0; mi < 4; mi++)
                ldsm_x4(af[mi], sbA + (wm * 64 + mi * 16 + rl) * AST + kb);
#pragma unroll
            for (int bi = 0; bi < 2; bi++)
                ldsm_x4(bf[bi], sbW + (wn * 32 + bi * 16 + rl) * AST + kb);
#pragma unroll
            for (int mi = 0; mi < 4; mi++)
#pragma unroll
            for (int ni = 0; ni < 4; ni++) {
                const int bi = ni >> 1, s = ni & 1;
                uint32_t bb[2] = {bf[bi][s], bf[bi][2 + s]};
                mma_f16(acc[mi][ni], af[mi], bb);
            }
        }
        __syncthreads();
    }

    // fused epilogue: tanh + dot(walpha), reduce to per-row score partials
    float pr0[4], pr1[4];
#pragma unroll
    for (int mi = 0; mi < 4; mi++) { pr0[mi] = 0.f; pr1[mi] = 0.f; }
#pragma unroll
    for (int mi = 0; mi < 4; mi++) {
        const int rl0 = wm * 64 + mi * 16 + (lane >> 2);
        const int bsel = rl0 >> 6;
#pragma unroll
        for (int ni = 0; ni < 4; ni++) {
            const int colL = wn * 32 + ni * 8 + ((lane & 3) << 1);
            float a0 = smAtth[bsel * 128 + colL];
            float a1 = smAtth[bsel * 128 + colL + 1];
            float w0 = smWal[colL], w1 = smWal[colL + 1];
            pr0[mi] += tanhf(acc[mi][ni][0] + a0) * w0 + tanhf(acc[mi][ni][1] + a1) * w1;
            pr1[mi] += tanhf(acc[mi][ni][2] + a0) * w0 + tanhf(acc[mi][ni][3] + a1) * w1;
        }
    }
#pragma unroll
    for (int mi = 0; mi < 4; mi++) {
        pr0[mi] += __shfl_xor_sync(0xffffffffu, pr0[mi], 1);
        pr0[mi] += __shfl_xor_sync(0xffffffffu, pr0[mi], 2);
        pr1[mi] += __shfl_xor_sync(0xffffffffu, pr1[mi], 1);
        pr1[mi] += __shfl_xor_sync(0xffffffffu, pr1[mi], 2);
        if ((lane & 3) == 0) {
            const int rl0 = wm * 64 + mi * 16 + (lane >> 2);
            atomicAdd(&sc[rl0], pr0[mi]);
            atomicAdd(&sc[rl0 + 8], pr1[mi]);
        }
    }
    __syncthreads();
    if (t < 128) scores_part[(size_t)bx * BS_ + bm + t] = sc[t];
}

// ---------------- masked softmax over S (one warp per b), 4 N-partials -------
__global__ void softmax_kernel(const float* __restrict__ parts, const int* __restrict__ mask,
                               float* __restrict__ wts)
{
    int b = blockIdx.x;
    int lane = threadIdx.x;
    int r0 = b * S_ + lane, r1 = r0 + 32;
    float x0 = 0.f, x1 = 0.f;
#pragma unroll
    for (int p = 0; p < 4; p++) { x0 += parts[(size_t)p * BS_ + r0]; x1 += parts[(size_t)p * BS_ + r1]; }
    float mx = fmaxf(x0, x1);
#pragma unroll
    for (int o = 16; o > 0; o >>= 1) mx = fmaxf(mx, __shfl_xor_sync(0xffffffffu, mx, o));
    float m0 = (float)mask[r0];
    float m1 = (float)mask[r1];
    float n0 = expf(x0 - mx) * m0;
    float n1 = expf(x1 - mx) * m1;
    float z = n0 + n1;
#pragma unroll
    for (int o = 16; o > 0; o >>= 1) z += __shfl_xor_sync(0xffffffffu, z, o);
    float inv = 1.f / z;
    wts[r0] = n0 * inv;
    wts[r1] = n1 * inv;
}

// ---------------- attout[b,d] = sum_s wts[b,s] * clip[b,s,d] -----------------
__global__ void attsum_kernel(const float* __restrict__ clip, const float* __restrict__ wts,
                              float* __restrict__ attout)
{
    int b = blockIdx.x;
    int t = threadIdx.x;
    __shared__ float w[S_];
    if (t < S_) w[t] = wts[b * S_ + t];
    __syncthreads();
    const float4* cb = (const float4*)(clip + (long)b * S_ * 1024);
    float4 acc = make_float4(0.f, 0.f, 0.f, 0.f);
#pragma unroll 8
    for (int s = 0; s < S_; s++) {
        float ws = w[s];
        float4 v = cb[s * 256 + t];
        acc.x = fmaf(ws, v.x, acc.x);
        acc.y = fmaf(ws, v.y, acc.y);
        acc.z = fmaf(ws, v.z, acc.z);
        acc.w = fmaf(ws, v.w, acc.w);
    }
    ((float4*)attout)[(long)b * 256 + t] = acc;
}

// ---------------- LSTM pointwise ----------------
__device__ __forceinline__ float sigm(float x) { return 1.f / (1.f + expf(-x)); }

__global__ void lstm_act(const float* __restrict__ gates, const float* __restrict__ cprev,
                         float* __restrict__ out_half, float* __restrict__ nh, float* __restrict__ nc)
{
    long i = (long)blockIdx.x * blockDim.x + threadIdx.x;
    if (i >= (long)B_ * R_) return;
    long b = i >> 10;
    int r = (int)(i & (R_ - 1));
    const float* g = gates + b * (4 * R_);
    float iv = sigm(g[r]);
    float fv = sigm(g[R_ + r]);
    float gv = tanhf(g[2 * R_ + r]);
    float ov = sigm(g[3 * R_ + r]);
    float c = fv * cprev[i] + iv * gv;
    float h = ov * tanhf(c);
    out_half[b * (2 * R_) + r] = h;
    nh[i] = h;
    nc[i] = c;
}

// ---------------- launch ----------------
extern "C" void kernel_launch(void* const* d_in, const int* in_sizes, int n_in,
                              void* d_out, int out_size)
{
    (void)in_sizes; (void)n_in; (void)out_size;
    const float* xt      = (const float*)d_in[0];
    const float* event   = (const float*)d_in[2];
    const float* clip    = (const float*)d_in[3];
    const int*   clip_mask = (const int*)d_in[4];
    const float* state_h = (const float*)d_in[5];
    const float* state_c = (const float*)d_in[6];
    const float* W_ih0   = (const float*)d_in[7];
    const float* b_ih0   = (const float*)d_in[8];
    const float* W_hh0   = (const float*)d_in[9];
    const float* b_hh0   = (const float*)d_in[10];
    const float* W_ih1   = (const float*)d_in[11];
    const float* b_ih1   = (const float*)d_in[12];
    const float* W_hh1   = (const float*)d_in[13];
    const float* b_hh1   = (const float*)d_in[14];
    const float* W_ctx   = (const float*)d_in[15];
    const float* b_ctx   = (const float*)d_in[16];
    const float* W_h2a   = (const float*)d_in[17];
    const float* b_h2a   = (const float*)d_in[18];
    const float* W_alpha = (const float*)d_in[19];

    float* out  = (float*)d_out;
    float* newh = out + (long)B_ * 2 * R_;
    float* newc = newh + 2L * B_ * R_;

    float *gates0, *gates1, *atth, *scores4, *wts, *attout;
    cudaGetSymbolAddress((void**)&gates0, g_gates0);
    cudaGetSymbolAddress((void**)&gates1, g_gates1);
    cudaGetSymbolAddress((void**)&atth,   g_atth);
    cudaGetSymbolAddress((void**)&scores4, g_scores4);
    cudaGetSymbolAddress((void**)&wts,    g_wts);
    cudaGetSymbolAddress((void**)&attout, g_attout);

    const float* h0 = state_h;
    const float* h1 = state_h + (long)B_ * R_;
    const float* c0 = state_c;
    const float* c1 = state_c + (long)B_ * R_;

    // 1) gates0 = [xt|event|h0] @ [W_ih0|W_hh0]^T + b_ih0 + b_hh0
    mma_gemm_split<<<dim3(32, 8), 256>>>(xt, event, h0, W_ih0, W_hh0, 2048, 1024, 3072,
                                         b_ih0, b_hh0, gates0, 4096);
    // 2) atth = h1 @ W_h2a^T + b_h2a + b_ctx
    mma_gemm_split<<<dim3(4, 8), 256>>>(h1, h1, h1, W_h2a, W_h2a, 1024, 1024, 1024,
                                        b_h2a, b_ctx, atth, 512);
    // 3) fused attention scores (fp16 single-pass), 4 H-partials
    mma_att<<<dim3(4, 512), 256>>>(clip, W_ctx, atth, W_alpha, scores4);
    // 4) masked softmax (b_alpha shift-invariant)
    softmax_kernel<<<B_, 32>>>(scores4, clip_mask, wts);
    // 5) attout = weights @ clip
    attsum_kernel<<<B_, 256>>>(clip, wts, attout);
    // 6) gates1 = [xt|attout|h1] @ [W_ih1|W_hh1]^T + b_ih1 + b_hh1
    mma_gemm_split<<<dim3(32, 8), 256>>>(xt, attout, h1, W_ih1, W_hh1, 2048, 1024, 3072,
                                         b_ih1, b_hh1, gates1, 4096);
    // 7) LSTM pointwise
    {
        int threads = 256;
        int blocks = (int)(((long)B_ * R_ + threads - 1) / threads);
        lstm_act<<<blocks, threads>>>(gates0, c0, out,      newh,                 newc);
        lstm_act<<<blocks, threads>>>(gates1, c1, out + R_, newh + (long)B_ * R_, newc + (long)B_ * R_);
    }
}

// round 11
// speedup vs baseline: 2.4704x; 1.2300x over previous
#include <cuda_runtime.h>
#include <cuda_bf16.h>
#include <cuda_fp16.h>
#include <cstdint>
#include <cstring>

// Problem dims (fixed)
#define B_  1024
#define S_  64
#define R_  1024
#define H_  512
#define BS_ (B_ * S_)     // 65536

#define AST 80            // smem row stride bytes: 32 elems * 2B + 16B pad

// ---------------------------------------------------------------------------
// scratch
// ---------------------------------------------------------------------------
__device__ float g_gates0[(size_t)B_ * 4 * R_];
__device__ float g_gates1[(size_t)B_ * 4 * R_];
__device__ float g_atth[(size_t)B_ * H_];
__device__ float g_scores2[(size_t)2 * BS_];
__device__ float g_wts[(size_t)B_ * S_];
__device__ float g_attout[(size_t)B_ * R_];

// ---------------------------------------------------------------------------
// PTX wrappers (baseline ISA: ldmatrix + mma.sync + tanh.approx, sm_80+)
// ---------------------------------------------------------------------------
__device__ __forceinline__ uint32_t smem_u32(const void* p) {
    uint32_t a;
    asm("{ .reg .u64 t; cvta.to.shared.u64 t, %1; cvt.u32.u64 %0, t; }" : "=r"(a) : "l"(p));
    return a;
}
__device__ __forceinline__ void ldsm_x4(uint32_t* r, uint32_t addr) {
    asm volatile("ldmatrix.sync.aligned.m8n8.x4.shared.b16 {%0,%1,%2,%3}, [%4];"
                 : "=r"(r[0]), "=r"(r[1]), "=r"(r[2]), "=r"(r[3]) : "r"(addr));
}
__device__ __forceinline__ void mma_bf16(float* d, const uint32_t* a, const uint32_t* b) {
    asm volatile("mma.sync.aligned.m16n8k16.row.col.f32.bf16.bf16.f32 "
                 "{%0,%1,%2,%3}, {%4,%5,%6,%7}, {%8,%9}, {%0,%1,%2,%3};"
                 : "+f"(d[0]), "+f"(d[1]), "+f"(d[2]), "+f"(d[3])
                 : "r"(a[0]), "r"(a[1]), "r"(a[2]), "r"(a[3]), "r"(b[0]), "r"(b[1]));
}
__device__ __forceinline__ void mma_f16(float* d, const uint32_t* a, const uint32_t* b) {
    asm volatile("mma.sync.aligned.m16n8k16.row.col.f32.f16.f16.f32 "
                 "{%0,%1,%2,%3}, {%4,%5,%6,%7}, {%8,%9}, {%0,%1,%2,%3};"
                 : "+f"(d[0]), "+f"(d[1]), "+f"(d[2]), "+f"(d[3])
                 : "r"(a[0]), "r"(a[1]), "r"(a[2]), "r"(a[3]), "r"(b[0]), "r"(b[1]));
}
__device__ __forceinline__ float tanh_fast(float x) {
    float y;
    asm("tanh.approx.f32 %0, %1;" : "=f"(y) : "f"(x));
    return y;
}
__device__ __forceinline__ uint32_t bf2u(__nv_bfloat162 h) { uint32_t u; memcpy(&u, &h, 4); return u; }
__device__ __forceinline__ uint32_t hf2u(__half2 h)        { uint32_t u; memcpy(&u, &h, 4); return u; }

// 8 fp32 (2 float4) -> uint4 of bf16 hi + uint4 of bf16 lo
__device__ __forceinline__ void cvt8_bf(const float4* v, uint4* hi, uint4* lo) {
    uint32_t h[4], l[4];
#pragma unroll
    for (int i = 0; i < 2; i++) {
        float2 xy = make_float2(v[i].x, v[i].y), zw = make_float2(v[i].z, v[i].w);
        __nv_bfloat162 hxy = __float22bfloat162_rn(xy), hzw = __float22bfloat162_rn(zw);
        float2 bxy = __bfloat1622float2(hxy), bzw = __bfloat1622float2(hzw);
        __nv_bfloat162 lxy = __float22bfloat162_rn(make_float2(xy.x - bxy.x, xy.y - bxy.y));
        __nv_bfloat162 lzw = __float22bfloat162_rn(make_float2(zw.x - bzw.x, zw.y - bzw.y));
        h[2*i] = bf2u(hxy); h[2*i+1] = bf2u(hzw);
        l[2*i] = bf2u(lxy); l[2*i+1] = bf2u(lzw);
    }
    *hi = make_uint4(h[0], h[1], h[2], h[3]);
    *lo = make_uint4(l[0], l[1], l[2], l[3]);
}
// 8 fp32 -> uint4 of fp16
__device__ __forceinline__ uint4 cvt8_f16(const float4* v) {
    uint32_t h[4];
#pragma unroll
    for (int i = 0; i < 2; i++) {
        h[2*i]   = hf2u(__float22half2_rn(make_float2(v[i].x, v[i].y)));
        h[2*i+1] = hf2u(__float22half2_rn(make_float2(v[i].z, v[i].w)));
    }
    return make_uint4(h[0], h[1], h[2], h[3]);
}

// ---------------------------------------------------------------------------
// Split-bf16 3-term GEMM: C[M,N] = A @ W^T + b1 + b2.  fp32 in/out.
// A: up to 3 segments of width 1024; W: 2 segments widths WK1, WK2.
// CTA tile 128(M)x256(N), 512 threads (4x4 warps, warp tile 32x64),
// K-chunk 32, double-buffered dynamic smem (2 x 61440 B), 1 barrier/chunk.
// ---------------------------------------------------------------------------
#define GBUF 61440
// per-buffer layout: Ahi 0 (10240), Alo 10240, Whi 20480 (20480), Wlo 40960

__global__ __launch_bounds__(512, 1)
void gemm_bf16x3(const float* __restrict__ A0, const float* __restrict__ A1,
                 const float* __restrict__ A2,
                 const float* __restrict__ W0, const float* __restrict__ W1,
                 int WK1, int WK2, int K,
                 const float* __restrict__ b1, const float* __restrict__ b2,
                 float* __restrict__ C, int N)
{
    extern __shared__ __align__(16) char sm[];
    const int t = threadIdx.x, lane = t & 31, wid = t >> 5;
    const int wm = wid >> 2, wn = wid & 3;     // 4 x 4 warps
    const long bm = (long)blockIdx.y * 128;
    const long bn = (long)blockIdx.x * 256;
    const float* Aseg[3] = {A0, A1, A2};
    const int ar = t >> 2, aq = t & 3;         // A: row, 8-float quarter
    const int wr = t >> 1, wh = t & 1;         // W: row, 16-float half

    float acc[2][8][4];
#pragma unroll
    for (int i = 0; i < 2; i++)
#pragma unroll
        for (int j = 0; j < 8; j++)
#pragma unroll
            for (int k = 0; k < 4; k++) acc[i][j][k] = 0.f;

    float4 pa[2], pw[4];
    // load + store chunk 0
    {
        const float4* ap = (const float4*)(Aseg[0] + (bm + ar) * 1024L + aq * 8);
        pa[0] = ap[0]; pa[1] = ap[1];
        const float4* wp = (const float4*)(W0 + (bn + wr) * (long)WK1 + wh * 16);
#pragma unroll
        for (int i = 0; i < 4; i++) pw[i] = wp[i];
        uint4 hi, lo;
        cvt8_bf(pa, &hi, &lo);
        *(uint4*)(sm + ar * AST + aq * 16) = hi;
        *(uint4*)(sm + 10240 + ar * AST + aq * 16) = lo;
        cvt8_bf(pw, &hi, &lo);
        *(uint4*)(sm + 20480 + wr * AST + wh * 32) = hi;
        *(uint4*)(sm + 40960 + wr * AST + wh * 32) = lo;
        cvt8_bf(pw + 2, &hi, &lo);
        *(uint4*)(sm + 20480 + wr * AST + wh * 32 + 16) = hi;
        *(uint4*)(sm + 40960 + wr * AST + wh * 32 + 16) = lo;
    }
    __syncthreads();

    const int NC = K >> 5;
    for (int c = 0; c < NC; c++) {
        const uint32_t sbA = smem_u32(sm) + (c & 1) * GBUF;
        const uint32_t sbW = sbA + 20480;
        // prefetch chunk c+1 into registers (hidden behind MMAs)
        if (c + 1 < NC) {
            const int k0 = (c + 1) << 5;
            const float4* ap = (const float4*)(Aseg[k0 >> 10] + (bm + ar) * 1024L + (k0 & 1023) + aq * 8);
            pa[0] = ap[0]; pa[1] = ap[1];
            const float* wb = (k0 < WK1) ? (W0 + (bn + wr) * (long)WK1 + k0)
                                         : (W1 + (bn + wr) * (long)WK2 + (k0 - WK1));
            const float4* wp = (const float4*)(wb + wh * 16);
#pragma unroll
            for (int i = 0; i < 4; i++) pw[i] = wp[i];
        }
        // compute on buffer c
#pragma unroll
        for (int ks = 0; ks < 2; ks++) {
            const uint32_t kb = ks * 32 + ((lane >> 4) << 4);
            const int rl = lane & 15;
            uint32_t ahi[2][4], alo[2][4];
#pragma unroll
            for (int mi = 0; mi < 2; mi++) {
                uint32_t off = (wm * 32 + mi * 16 + rl) * AST + kb;
                ldsm_x4(ahi[mi], sbA + off);
                ldsm_x4(alo[mi], sbA + 10240 + off);
            }
#pragma unroll
            for (int bi = 0; bi < 4; bi++) {
                uint32_t off = (wn * 64 + bi * 16 + rl) * AST + kb;
                uint32_t bhi[4], blo[4];
                ldsm_x4(bhi, sbW + off);
                ldsm_x4(blo, sbW + 20480 + off);
#pragma unroll
                for (int mi = 0; mi < 2; mi++)
#pragma unroll
                for (int s = 0; s < 2; s++) {
                    const int ni = bi * 2 + s;
                    uint32_t bh[2] = {bhi[s], bhi[2 + s]};
                    uint32_t bl[2] = {blo[s], blo[2 + s]};
                    mma_bf16(acc[mi][ni], ahi[mi], bh);
                    mma_bf16(acc[mi][ni], ahi[mi], bl);
                    mma_bf16(acc[mi][ni], alo[mi], bh);
                }
            }
        }
        // store chunk c+1 into the other buffer
        if (c + 1 < NC) {
            char* nb = sm + ((c + 1) & 1) * GBUF;
            uint4 hi, lo;
            cvt8_bf(pa, &hi, &lo);
            *(uint4*)(nb + ar * AST + aq * 16) = hi;
            *(uint4*)(nb + 10240 + ar * AST + aq * 16) = lo;
            cvt8_bf(pw, &hi, &lo);
            *(uint4*)(nb + 20480 + wr * AST + wh * 32) = hi;
            *(uint4*)(nb + 40960 + wr * AST + wh * 32) = lo;
            cvt8_bf(pw + 2, &hi, &lo);
            *(uint4*)(nb + 20480 + wr * AST + wh * 32 + 16) = hi;
            *(uint4*)(nb + 40960 + wr * AST + wh * 32 + 16) = lo;
        }
        __syncthreads();
    }

    // epilogue: += biases, write fp32
#pragma unroll
    for (int mi = 0; mi < 2; mi++) {
        const long r0 = bm + wm * 32 + mi * 16 + (lane >> 2);
#pragma unroll
        for (int ni = 0; ni < 8; ni++) {
            const long col = bn + wn * 64 + ni * 8 + ((lane & 3) << 1);
            const float bb0 = b1[col] + b2[col];
            const float bb1 = b1[col + 1] + b2[col + 1];
            *(float2*)(C + r0 * N + col) =
                make_float2(acc[mi][ni][0] + bb0, acc[mi][ni][1] + bb1);
            *(float2*)(C + (r0 + 8) * N + col) =
                make_float2(acc[mi][ni][2] + bb0, acc[mi][ni][3] + bb1);
        }
    }
}

// ---------------------------------------------------------------------------
// Attention GEMM (fp16 single-pass) + fused score epilogue.
// scores_part[bx*BS + m] = sum_{h in 256-tile} tanh(gemm[m,h] + atth[b,h]) * walpha[h]
// M=65536 (clip rows), N=512 (H), K=1024. CTA 128x256, grid (2, 512).
// ---------------------------------------------------------------------------
#define ABUF 30720
// per-buffer: A 0 (10240), W 10240 (20480)

__global__ __launch_bounds__(512, 1)
void att_f16(const float* __restrict__ clip, const float* __restrict__ Wc,
             const float* __restrict__ atth, const float* __restrict__ walpha,
             float* __restrict__ scores_part)
{
    extern __shared__ __align__(16) char sm[];
    __shared__ float smAtth[512];   // 2 batches x 256 cols
    __shared__ float smWal[256];
    __shared__ float sc[128];

    const int t = threadIdx.x, lane = t & 31, wid = t >> 5;
    const int wm = wid >> 2, wn = wid & 3;
    const long bm = (long)blockIdx.y * 128;
    const int bx = blockIdx.x;
    const long bn = (long)bx * 256;
    const int ar = t >> 2, aq = t & 3;
    const int wr = t >> 1, wh = t & 1;

    smAtth[t] = atth[(size_t)((bm >> 6) + (t >> 8)) * H_ + bn + (t & 255)];
    if (t < 256) smWal[t] = walpha[bn + t];
    if (t < 128) sc[t] = 0.f;

    float acc[2][8][4];
#pragma unroll
    for (int i = 0; i < 2; i++)
#pragma unroll
        for (int j = 0; j < 8; j++)
#pragma unroll
            for (int k = 0; k < 4; k++) acc[i][j][k] = 0.f;

    float4 pa[2], pw[4];
    {
        const float4* ap = (const float4*)(clip + (bm + ar) * 1024L + aq * 8);
        pa[0] = ap[0]; pa[1] = ap[1];
        const float4* wp = (const float4*)(Wc + (bn + wr) * 1024L + wh * 16);
#pragma unroll
        for (int i = 0; i < 4; i++) pw[i] = wp[i];
        *(uint4*)(sm + ar * AST + aq * 16) = cvt8_f16(pa);
        *(uint4*)(sm + 10240 + wr * AST + wh * 32) = cvt8_f16(pw);
        *(uint4*)(sm + 10240 + wr * AST + wh * 32 + 16) = cvt8_f16(pw + 2);
    }
    __syncthreads();

    const int NC = 1024 >> 5;   // 32
    for (int c = 0; c < NC; c++) {
        const uint32_t sbA = smem_u32(sm) + (c & 1) * ABUF;
        const uint32_t sbW = sbA + 10240;
        if (c + 1 < NC) {
            const int k0 = (c + 1) << 5;
            const float4* ap = (const float4*)(clip + (bm + ar) * 1024L + k0 + aq * 8);
            pa[0] = ap[0]; pa[1] = ap[1];
            const float4* wp = (const float4*)(Wc + (bn + wr) * 1024L + k0 + wh * 16);
#pragma unroll
            for (int i = 0; i < 4; i++) pw[i] = wp[i];
        }
#pragma unroll
        for (int ks = 0; ks < 2; ks++) {
            const uint32_t kb = ks * 32 + ((lane >> 4) << 4);
            const int rl = lane & 15;
            uint32_t af[2][4];
#pragma unroll
            for (int mi = 0; mi < 2; mi++)
                ldsm_x4(af[mi], sbA + (wm * 32 + mi * 16 + rl) * AST + kb);
#pragma unroll
            for (int bi = 0; bi < 4; bi++) {
                uint32_t bf[4];
                ldsm_x4(bf, sbW + (wn * 64 + bi * 16 + rl) * AST + kb);
#pragma unroll
                for (int mi = 0; mi < 2; mi++)
#pragma unroll
                for (int s = 0; s < 2; s++) {
                    uint32_t bb[2] = {bf[s], bf[2 + s]};
                    mma_f16(acc[mi][bi * 2 + s], af[mi], bb);
                }
            }
        }
        if (c + 1 < NC) {
            char* nb = sm + ((c + 1) & 1) * ABUF;
            *(uint4*)(nb + ar * AST + aq * 16) = cvt8_f16(pa);
            *(uint4*)(nb + 10240 + wr * AST + wh * 32) = cvt8_f16(pw);
            *(uint4*)(nb + 10240 + wr * AST + wh * 32 + 16) = cvt8_f16(pw + 2);
        }
        __syncthreads();
    }

    // fused epilogue: tanh + dot(walpha) -> per-row partial scores
#pragma unroll
    for (int mi = 0; mi < 2; mi++) {
        const int rlo = wm * 32 + mi * 16 + (lane >> 2);
        const int bsel = rlo >> 6;
        float pr0 = 0.f, pr1 = 0.f;
#pragma unroll
        for (int ni = 0; ni < 8; ni++) {
            const int colC = wn * 64 + ni * 8 + ((lane & 3) << 1);
            const float a0 = smAtth[bsel * 256 + colC];
            const float a1 = smAtth[bsel * 256 + colC + 1];
            const float w0 = smWal[colC], w1 = smWal[colC + 1];
            pr0 += tanh_fast(acc[mi][ni][0] + a0) * w0 + tanh_fast(acc[mi][ni][1] + a1) * w1;
            pr1 += tanh_fast(acc[mi][ni][2] + a0) * w0 + tanh_fast(acc[mi][ni][3] + a1) * w1;
        }
        pr0 += __shfl_xor_sync(0xffffffffu, pr0, 1);
        pr0 += __shfl_xor_sync(0xffffffffu, pr0, 2);
        pr1 += __shfl_xor_sync(0xffffffffu, pr1, 1);
        pr1 += __shfl_xor_sync(0xffffffffu, pr1, 2);
        if ((lane & 3) == 0) {
            atomicAdd(&sc[rlo], pr0);
            atomicAdd(&sc[rlo + 8], pr1);
        }
    }
    __syncthreads();
    if (t < 128) scores_part[(size_t)bx * BS_ + bm + t] = sc[t];
}

// ---------------- masked softmax over S (one warp per b), 2 H-partials -------
__global__ void softmax_kernel(const float* __restrict__ parts, const int* __restrict__ mask,
                               float* __restrict__ wts)
{
    int b = blockIdx.x;
    int lane = threadIdx.x;
    int r0 = b * S_ + lane, r1 = r0 + 32;
    float x0 = parts[r0] + parts[BS_ + r0];
    float x1 = parts[r1] + parts[BS_ + r1];
    float mx = fmaxf(x0, x1);
#pragma unroll
    for (int o = 16; o > 0; o >>= 1) mx = fmaxf(mx, __shfl_xor_sync(0xffffffffu, mx, o));
    float m0 = (float)mask[r0];
    float m1 = (float)mask[r1];
    float n0 = expf(x0 - mx) * m0;
    float n1 = expf(x1 - mx) * m1;
    float z = n0 + n1;
#pragma unroll
    for (int o = 16; o > 0; o >>= 1) z += __shfl_xor_sync(0xffffffffu, z, o);
    float inv = 1.f / z;
    wts[r0] = n0 * inv;
    wts[r1] = n1 * inv;
}

// ---------------- attout[b,d] = sum_s wts[b,s] * clip[b,s,d] -----------------
__global__ void attsum_kernel(const float* __restrict__ clip, const float* __restrict__ wts,
                              float* __restrict__ attout)
{
    int b = blockIdx.x;
    int t = threadIdx.x;
    __shared__ float w[S_];
    if (t < S_) w[t] = wts[b * S_ + t];
    __syncthreads();
    const float4* cb = (const float4*)(clip + (long)b * S_ * 1024);
    float4 acc = make_float4(0.f, 0.f, 0.f, 0.f);
#pragma unroll 8
    for (int s = 0; s < S_; s++) {
        float ws = w[s];
        float4 v = cb[s * 256 + t];
        acc.x = fmaf(ws, v.x, acc.x);
        acc.y = fmaf(ws, v.y, acc.y);
        acc.z = fmaf(ws, v.z, acc.z);
        acc.w = fmaf(ws, v.w, acc.w);
    }
    ((float4*)attout)[(long)b * 256 + t] = acc;
}

// ---------------- LSTM pointwise (precise tanh — output accuracy) ------------
__device__ __forceinline__ float sigm(float x) { return 1.f / (1.f + expf(-x)); }

__global__ void lstm_act(const float* __restrict__ gates, const float* __restrict__ cprev,
                         float* __restrict__ out_half, float* __restrict__ nh, float* __restrict__ nc)
{
    long i = (long)blockIdx.x * blockDim.x + threadIdx.x;
    if (i >= (long)B_ * R_) return;
    long b = i >> 10;
    int r = (int)(i & (R_ - 1));
    const float* g = gates + b * (4 * R_);
    float iv = sigm(g[r]);
    float fv = sigm(g[R_ + r]);
    float gv = tanhf(g[2 * R_ + r]);
    float ov = sigm(g[3 * R_ + r]);
    float c = fv * cprev[i] + iv * gv;
    float h = ov * tanhf(c);
    out_half[b * (2 * R_) + r] = h;
    nh[i] = h;
    nc[i] = c;
}

// ---------------- launch ----------------
extern "C" void kernel_launch(void* const* d_in, const int* in_sizes, int n_in,
                              void* d_out, int out_size)
{
    (void)in_sizes; (void)n_in; (void)out_size;
    const float* xt      = (const float*)d_in[0];
    const float* event   = (const float*)d_in[2];
    const float* clip    = (const float*)d_in[3];
    const int*   clip_mask = (const int*)d_in[4];
    const float* state_h = (const float*)d_in[5];
    const float* state_c = (const float*)d_in[6];
    const float* W_ih0   = (const float*)d_in[7];
    const float* b_ih0   = (const float*)d_in[8];
    const float* W_hh0   = (const float*)d_in[9];
    const float* b_hh0   = (const float*)d_in[10];
    const float* W_ih1   = (const float*)d_in[11];
    const float* b_ih1   = (const float*)d_in[12];
    const float* W_hh1   = (const float*)d_in[13];
    const float* b_hh1   = (const float*)d_in[14];
    const float* W_ctx   = (const float*)d_in[15];
    const float* b_ctx   = (const float*)d_in[16];
    const float* W_h2a   = (const float*)d_in[17];
    const float* b_h2a   = (const float*)d_in[18];
    const float* W_alpha = (const float*)d_in[19];

    float* out  = (float*)d_out;
    float* newh = out + (long)B_ * 2 * R_;
    float* newc = newh + 2L * B_ * R_;

    float *gates0, *gates1, *atth, *scores2, *wts, *attout;
    cudaGetSymbolAddress((void**)&gates0, g_gates0);
    cudaGetSymbolAddress((void**)&gates1, g_gates1);
    cudaGetSymbolAddress((void**)&atth,   g_atth);
    cudaGetSymbolAddress((void**)&scores2, g_scores2);
    cudaGetSymbolAddress((void**)&wts,    g_wts);
    cudaGetSymbolAddress((void**)&attout, g_attout);

    const float* h0 = state_h;
    const float* h1 = state_h + (long)B_ * R_;
    const float* c0 = state_c;
    const float* c1 = state_c + (long)B_ * R_;

    cudaFuncSetAttribute(gemm_bf16x3, cudaFuncAttributeMaxDynamicSharedMemorySize, 2 * GBUF);
    cudaFuncSetAttribute(att_f16,     cudaFuncAttributeMaxDynamicSharedMemorySize, 2 * ABUF);

    // 1) gates0 = [xt|event|h0] @ [W_ih0|W_hh0]^T + b_ih0 + b_hh0
    gemm_bf16x3<<<dim3(16, 8), 512, 2 * GBUF>>>(xt, event, h0, W_ih0, W_hh0, 2048, 1024, 3072,
                                                b_ih0, b_hh0, gates0, 4096);
    // 2) atth = h1 @ W_h2a^T + b_h2a + b_ctx
    gemm_bf16x3<<<dim3(2, 8), 512, 2 * GBUF>>>(h1, h1, h1, W_h2a, W_h2a, 1024, 1024, 1024,
                                               b_h2a, b_ctx, atth, 512);
    // 3) fused attention scores (fp16), 2 H-partials
    att_f16<<<dim3(2, 512), 512, 2 * ABUF>>>(clip, W_ctx, atth, W_alpha, scores2);
    // 4) masked softmax (b_alpha shift-invariant)
    softmax_kernel<<<B_, 32>>>(scores2, clip_mask, wts);
    // 5) attout = weights @ clip
    attsum_kernel<<<B_, 256>>>(clip, wts, attout);
    // 6) gates1 = [xt|attout|h1] @ [W_ih1|W_hh1]^T + b_ih1 + b_hh1
    gemm_bf16x3<<<dim3(16, 8), 512, 2 * GBUF>>>(xt, attout, h1, W_ih1, W_hh1, 2048, 1024, 3072,
                                                b_ih1, b_hh1, gates1, 4096);
    // 7) LSTM pointwise
    {
        int threads = 256;
        int blocks = (int)(((long)B_ * R_ + threads - 1) / threads);
        lstm_act<<<blocks, threads>>>(gates0, c0, out,      newh,                 newc);
        lstm_act<<<blocks, threads>>>(gates1, c1, out + R_, newh + (long)B_ * R_, newc + (long)B_ * R_);
    }
}

// round 12
// speedup vs baseline: 2.9413x; 1.1906x over previous
#include <cuda_runtime.h>
#include <cuda_bf16.h>
#include <cuda_fp16.h>
#include <cstdint>
#include <cstring>

// Problem dims (fixed)
#define B_  1024
#define S_  64
#define R_  1024
#define H_  512
#define BS_ (B_ * S_)     // 65536

#define AST 80            // smem row stride bytes: 32 elems * 2B + 16B pad

// ---------------------------------------------------------------------------
// scratch
// ---------------------------------------------------------------------------
__device__ float g_gates0[(size_t)B_ * 4 * R_];
__device__ float g_gates1[(size_t)B_ * 4 * R_];
__device__ float g_atth[(size_t)B_ * H_];
__device__ float g_scores2[(size_t)2 * BS_];
__device__ float g_wts[(size_t)B_ * S_];
__device__ float g_attout[(size_t)B_ * R_];

// ---------------------------------------------------------------------------
// PTX wrappers (baseline ISA: ldmatrix + mma.sync + tanh.approx, sm_80+)
// ---------------------------------------------------------------------------
__device__ __forceinline__ uint32_t smem_u32(const void* p) {
    uint32_t a;
    asm("{ .reg .u64 t; cvta.to.shared.u64 t, %1; cvt.u32.u64 %0, t; }" : "=r"(a) : "l"(p));
    return a;
}
__device__ __forceinline__ void ldsm_x4(uint32_t* r, uint32_t addr) {
    asm volatile("ldmatrix.sync.aligned.m8n8.x4.shared.b16 {%0,%1,%2,%3}, [%4];"
                 : "=r"(r[0]), "=r"(r[1]), "=r"(r[2]), "=r"(r[3]) : "r"(addr));
}
__device__ __forceinline__ void mma_f16(float* d, const uint32_t* a, const uint32_t* b) {
    asm volatile("mma.sync.aligned.m16n8k16.row.col.f32.f16.f16.f32 "
                 "{%0,%1,%2,%3}, {%4,%5,%6,%7}, {%8,%9}, {%0,%1,%2,%3};"
                 : "+f"(d[0]), "+f"(d[1]), "+f"(d[2]), "+f"(d[3])
                 : "r"(a[0]), "r"(a[1]), "r"(a[2]), "r"(a[3]), "r"(b[0]), "r"(b[1]));
}
__device__ __forceinline__ float tanh_fast(float x) {
    float y;
    asm("tanh.approx.f32 %0, %1;" : "=f"(y) : "f"(x));
    return y;
}
__device__ __forceinline__ uint32_t hf2u(__half2 h) { uint32_t u; memcpy(&u, &h, 4); return u; }

// 8 fp32 -> uint4 of fp16
__device__ __forceinline__ uint4 cvt8_f16(const float4* v) {
    uint32_t h[4];
#pragma unroll
    for (int i = 0; i < 2; i++) {
        h[2*i]   = hf2u(__float22half2_rn(make_float2(v[i].x, v[i].y)));
        h[2*i+1] = hf2u(__float22half2_rn(make_float2(v[i].z, v[i].w)));
    }
    return make_uint4(h[0], h[1], h[2], h[3]);
}
// 8 fp32 -> fp16 hi + fp16 lo (residual), 1x uint4 each
__device__ __forceinline__ void cvt8_f16_split(const float4* v, uint4* hi, uint4* lo) {
    uint32_t h[4], l[4];
#pragma unroll
    for (int i = 0; i < 2; i++) {
        float2 xy = make_float2(v[i].x, v[i].y), zw = make_float2(v[i].z, v[i].w);
        __half2 hxy = __float22half2_rn(xy), hzw = __float22half2_rn(zw);
        float2 bxy = __half22float2(hxy), bzw = __half22float2(hzw);
        __half2 lxy = __float22half2_rn(make_float2(xy.x - bxy.x, xy.y - bxy.y));
        __half2 lzw = __float22half2_rn(make_float2(zw.x - bzw.x, zw.y - bzw.y));
        h[2*i] = hf2u(hxy); h[2*i+1] = hf2u(hzw);
        l[2*i] = hf2u(lxy); l[2*i+1] = hf2u(lzw);
    }
    *hi = make_uint4(h[0], h[1], h[2], h[3]);
    *lo = make_uint4(l[0], l[1], l[2], l[3]);
}

// ---------------------------------------------------------------------------
// 2-term fp16-split GEMM: C[M,N] = A @ W^T + b1 + b2.  fp32 in/out.
// A split hi+lo fp16 (near-exact); W single fp16 (rounding 2.4e-4).
// A: up to 3 segments of width 1024; W: 2 segments widths WK1, WK2.
// CTA tile 128(M)x256(N), 512 threads (4x4 warps, warp tile 32x64),
// K-chunk 32, double-buffered dynamic smem (2 x 40960 B), 1 barrier/chunk.
// ---------------------------------------------------------------------------
#define GBUF 40960
// per-buffer layout: Ahi 0 (10240), Alo 10240, W 20480 (20480)

__global__ __launch_bounds__(512, 1)
void gemm_f16x2(const float* __restrict__ A0, const float* __restrict__ A1,
                const float* __restrict__ A2,
                const float* __restrict__ W0, const float* __restrict__ W1,
                int WK1, int WK2, int K,
                const float* __restrict__ b1, const float* __restrict__ b2,
                float* __restrict__ C, int N)
{
    extern __shared__ __align__(16) char sm[];
    const int t = threadIdx.x, lane = t & 31, wid = t >> 5;
    const int wm = wid >> 2, wn = wid & 3;     // 4 x 4 warps
    const long bm = (long)blockIdx.y * 128;
    const long bn = (long)blockIdx.x * 256;
    const float* Aseg[3] = {A0, A1, A2};
    const int ar = t >> 2, aq = t & 3;         // A: row, 8-float quarter
    const int wr = t >> 1, wh = t & 1;         // W: row, 16-float half

    float acc[2][8][4];
#pragma unroll
    for (int i = 0; i < 2; i++)
#pragma unroll
        for (int j = 0; j < 8; j++)
#pragma unroll
            for (int k = 0; k < 4; k++) acc[i][j][k] = 0.f;

    float4 pa[2], pw[4];
    // load + store chunk 0
    {
        const float4* ap = (const float4*)(Aseg[0] + (bm + ar) * 1024L + aq * 8);
        pa[0] = ap[0]; pa[1] = ap[1];
        const float4* wp = (const float4*)(W0 + (bn + wr) * (long)WK1 + wh * 16);
#pragma unroll
        for (int i = 0; i < 4; i++) pw[i] = wp[i];
        uint4 hi, lo;
        cvt8_f16_split(pa, &hi, &lo);
        *(uint4*)(sm + ar * AST + aq * 16) = hi;
        *(uint4*)(sm + 10240 + ar * AST + aq * 16) = lo;
        *(uint4*)(sm + 20480 + wr * AST + wh * 32) = cvt8_f16(pw);
        *(uint4*)(sm + 20480 + wr * AST + wh * 32 + 16) = cvt8_f16(pw + 2);
    }
    __syncthreads();

    const int NC = K >> 5;
    for (int c = 0; c < NC; c++) {
        const uint32_t sbA = smem_u32(sm) + (c & 1) * GBUF;
        const uint32_t sbW = sbA + 20480;
        // prefetch chunk c+1 into registers (hidden behind MMAs)
        if (c + 1 < NC) {
            const int k0 = (c + 1) << 5;
            const float4* ap = (const float4*)(Aseg[k0 >> 10] + (bm + ar) * 1024L + (k0 & 1023) + aq * 8);
            pa[0] = ap[0]; pa[1] = ap[1];
            const float* wb = (k0 < WK1) ? (W0 + (bn + wr) * (long)WK1 + k0)
                                         : (W1 + (bn + wr) * (long)WK2 + (k0 - WK1));
            const float4* wp = (const float4*)(wb + wh * 16);
#pragma unroll
            for (int i = 0; i < 4; i++) pw[i] = wp[i];
        }
        // compute on buffer c
#pragma unroll
        for (int ks = 0; ks < 2; ks++) {
            const uint32_t kb = ks * 32 + ((lane >> 4) << 4);
            const int rl = lane & 15;
            uint32_t ahi[2][4], alo[2][4];
#pragma unroll
            for (int mi = 0; mi < 2; mi++) {
                uint32_t off = (wm * 32 + mi * 16 + rl) * AST + kb;
                ldsm_x4(ahi[mi], sbA + off);
                ldsm_x4(alo[mi], sbA + 10240 + off);
            }
#pragma unroll
            for (int bi = 0; bi < 4; bi++) {
                uint32_t off = (wn * 64 + bi * 16 + rl) * AST + kb;
                uint32_t bf[4];
                ldsm_x4(bf, sbW + off);
#pragma unroll
                for (int mi = 0; mi < 2; mi++)
#pragma unroll
                for (int s = 0; s < 2; s++) {
                    const int ni = bi * 2 + s;
                    uint32_t bb[2] = {bf[s], bf[2 + s]};
                    mma_f16(acc[mi][ni], ahi[mi], bb);
                    mma_f16(acc[mi][ni], alo[mi], bb);
                }
            }
        }
        // store chunk c+1 into the other buffer
        if (c + 1 < NC) {
            char* nb = sm + ((c + 1) & 1) * GBUF;
            uint4 hi, lo;
            cvt8_f16_split(pa, &hi, &lo);
            *(uint4*)(nb + ar * AST + aq * 16) = hi;
            *(uint4*)(nb + 10240 + ar * AST + aq * 16) = lo;
            *(uint4*)(nb + 20480 + wr * AST + wh * 32) = cvt8_f16(pw);
            *(uint4*)(nb + 20480 + wr * AST + wh * 32 + 16) = cvt8_f16(pw + 2);
        }
        __syncthreads();
    }

    // epilogue: += biases, write fp32
#pragma unroll
    for (int mi = 0; mi < 2; mi++) {
        const long r0 = bm + wm * 32 + mi * 16 + (lane >> 2);
#pragma unroll
        for (int ni = 0; ni < 8; ni++) {
            const long col = bn + wn * 64 + ni * 8 + ((lane & 3) << 1);
            const float bb0 = b1[col] + b2[col];
            const float bb1 = b1[col + 1] + b2[col + 1];
            *(float2*)(C + r0 * N + col) =
                make_float2(acc[mi][ni][0] + bb0, acc[mi][ni][1] + bb1);
            *(float2*)(C + (r0 + 8) * N + col) =
                make_float2(acc[mi][ni][2] + bb0, acc[mi][ni][3] + bb1);
        }
    }
}

// ---------------------------------------------------------------------------
// Attention GEMM (fp16 single-pass) + fused score epilogue.
// scores_part[bx*BS + m] = sum_{h in 256-tile} tanh(gemm[m,h] + atth[b,h]) * walpha[h]
// M=65536 (clip rows), N=512 (H), K=1024. CTA 128x256, grid (2, 512).
// ---------------------------------------------------------------------------
#define ABUF 30720
// per-buffer: A 0 (10240), W 10240 (20480)

__global__ __launch_bounds__(512, 1)
void att_f16(const float* __restrict__ clip, const float* __restrict__ Wc,
             const float* __restrict__ atth, const float* __restrict__ walpha,
             float* __restrict__ scores_part)
{
    extern __shared__ __align__(16) char sm[];
    __shared__ float smAtth[512];   // 2 batches x 256 cols
    __shared__ float smWal[256];
    __shared__ float sc[128];

    const int t = threadIdx.x, lane = t & 31, wid = t >> 5;
    const int wm = wid >> 2, wn = wid & 3;
    const long bm = (long)blockIdx.y * 128;
    const int bx = blockIdx.x;
    const long bn = (long)bx * 256;
    const int ar = t >> 2, aq = t & 3;
    const int wr = t >> 1, wh = t & 1;

    smAtth[t] = atth[(size_t)((bm >> 6) + (t >> 8)) * H_ + bn + (t & 255)];
    if (t < 256) smWal[t] = walpha[bn + t];
    if (t < 128) sc[t] = 0.f;

    float acc[2][8][4];
#pragma unroll
    for (int i = 0; i < 2; i++)
#pragma unroll
        for (int j = 0; j < 8; j++)
#pragma unroll
            for (int k = 0; k < 4; k++) acc[i][j][k] = 0.f;

    float4 pa[2], pw[4];
    {
        const float4* ap = (const float4*)(clip + (bm + ar) * 1024L + aq * 8);
        pa[0] = ap[0]; pa[1] = ap[1];
        const float4* wp = (const float4*)(Wc + (bn + wr) * 1024L + wh * 16);
#pragma unroll
        for (int i = 0; i < 4; i++) pw[i] = wp[i];
        *(uint4*)(sm + ar * AST + aq * 16) = cvt8_f16(pa);
        *(uint4*)(sm + 10240 + wr * AST + wh * 32) = cvt8_f16(pw);
        *(uint4*)(sm + 10240 + wr * AST + wh * 32 + 16) = cvt8_f16(pw + 2);
    }
    __syncthreads();

    const int NC = 1024 >> 5;   // 32
    for (int c = 0; c < NC; c++) {
        const uint32_t sbA = smem_u32(sm) + (c & 1) * ABUF;
        const uint32_t sbW = sbA + 10240;
        if (c + 1 < NC) {
            const int k0 = (c + 1) << 5;
            const float4* ap = (const float4*)(clip + (bm + ar) * 1024L + k0 + aq * 8);
            pa[0] = ap[0]; pa[1] = ap[1];
            const float4* wp = (const float4*)(Wc + (bn + wr) * 1024L + k0 + wh * 16);
#pragma unroll
            for (int i = 0; i < 4; i++) pw[i] = wp[i];
        }
#pragma unroll
        for (int ks = 0; ks < 2; ks++) {
            const uint32_t kb = ks * 32 + ((lane >> 4) << 4);
            const int rl = lane & 15;
            uint32_t af[2][4];
#pragma unroll
            for (int mi = 0; mi < 2; mi++)
                ldsm_x4(af[mi], sbA + (wm * 32 + mi * 16 + rl) * AST + kb);
#pragma unroll
            for (int bi = 0; bi < 4; bi++) {
                uint32_t bf[4];
                ldsm_x4(bf, sbW + (wn * 64 + bi * 16 + rl) * AST + kb);
#pragma unroll
                for (int mi = 0; mi < 2; mi++)
#pragma unroll
                for (int s = 0; s < 2; s++) {
                    uint32_t bb[2] = {bf[s], bf[2 + s]};
                    mma_f16(acc[mi][bi * 2 + s], af[mi], bb);
                }
            }
        }
        if (c + 1 < NC) {
            char* nb = sm + ((c + 1) & 1) * ABUF;
            *(uint4*)(nb + ar * AST + aq * 16) = cvt8_f16(pa);
            *(uint4*)(nb + 10240 + wr * AST + wh * 32) = cvt8_f16(pw);
            *(uint4*)(nb + 10240 + wr * AST + wh * 32 + 16) = cvt8_f16(pw + 2);
        }
        __syncthreads();
    }

    // fused epilogue: tanh + dot(walpha) -> per-row partial scores
#pragma unroll
    for (int mi = 0; mi < 2; mi++) {
        const int rlo = wm * 32 + mi * 16 + (lane >> 2);
        const int bsel = rlo >> 6;
        float pr0 = 0.f, pr1 = 0.f;
#pragma unroll
        for (int ni = 0; ni < 8; ni++) {
            const int colC = wn * 64 + ni * 8 + ((lane & 3) << 1);
            const float a0 = smAtth[bsel * 256 + colC];
            const float a1 = smAtth[bsel * 256 + colC + 1];
            const float w0 = smWal[colC], w1 = smWal[colC + 1];
            pr0 += tanh_fast(acc[mi][ni][0] + a0) * w0 + tanh_fast(acc[mi][ni][1] + a1) * w1;
            pr1 += tanh_fast(acc[mi][ni][2] + a0) * w0 + tanh_fast(acc[mi][ni][3] + a1) * w1;
        }
        pr0 += __shfl_xor_sync(0xffffffffu, pr0, 1);
        pr0 += __shfl_xor_sync(0xffffffffu, pr0, 2);
        pr1 += __shfl_xor_sync(0xffffffffu, pr1, 1);
        pr1 += __shfl_xor_sync(0xffffffffu, pr1, 2);
        if ((lane & 3) == 0) {
            atomicAdd(&sc[rlo], pr0);
            atomicAdd(&sc[rlo + 8], pr1);
        }
    }
    __syncthreads();
    if (t < 128) scores_part[(size_t)bx * BS_ + bm + t] = sc[t];
}

// ---------------- masked softmax over S (one warp per b), 2 H-partials -------
__global__ void softmax_kernel(const float* __restrict__ parts, const int* __restrict__ mask,
                               float* __restrict__ wts)
{
    int b = blockIdx.x;
    int lane = threadIdx.x;
    int r0 = b * S_ + lane, r1 = r0 + 32;
    float x0 = parts[r0] + parts[BS_ + r0];
    float x1 = parts[r1] + parts[BS_ + r1];
    float mx = fmaxf(x0, x1);
#pragma unroll
    for (int o = 16; o > 0; o >>= 1) mx = fmaxf(mx, __shfl_xor_sync(0xffffffffu, mx, o));
    float m0 = (float)mask[r0];
    float m1 = (float)mask[r1];
    float n0 = expf(x0 - mx) * m0;
    float n1 = expf(x1 - mx) * m1;
    float z = n0 + n1;
#pragma unroll
    for (int o = 16; o > 0; o >>= 1) z += __shfl_xor_sync(0xffffffffu, z, o);
    float inv = 1.f / z;
    wts[r0] = n0 * inv;
    wts[r1] = n1 * inv;
}

// ---------------- attout[b,d] = sum_s wts[b,s] * clip[b,s,d] -----------------
__global__ void attsum_kernel(const float* __restrict__ clip, const float* __restrict__ wts,
                              float* __restrict__ attout)
{
    int b = blockIdx.x;
    int t = threadIdx.x;
    __shared__ float w[S_];
    if (t < S_) w[t] = wts[b * S_ + t];
    __syncthreads();
    const float4* cb = (const float4*)(clip + (long)b * S_ * 1024);
    float4 acc = make_float4(0.f, 0.f, 0.f, 0.f);
#pragma unroll 8
    for (int s = 0; s < S_; s++) {
        float ws = w[s];
        float4 v = cb[s * 256 + t];
        acc.x = fmaf(ws, v.x, acc.x);
        acc.y = fmaf(ws, v.y, acc.y);
        acc.z = fmaf(ws, v.z, acc.z);
        acc.w = fmaf(ws, v.w, acc.w);
    }
    ((float4*)attout)[(long)b * 256 + t] = acc;
}

// ---------------- LSTM pointwise (precise tanh — output accuracy) ------------
__device__ __forceinline__ float sigm(float x) { return 1.f / (1.f + expf(-x)); }

__global__ void lstm_act(const float* __restrict__ gates, const float* __restrict__ cprev,
                         float* __restrict__ out_half, float* __restrict__ nh, float* __restrict__ nc)
{
    long i = (long)blockIdx.x * blockDim.x + threadIdx.x;
    if (i >= (long)B_ * R_) return;
    long b = i >> 10;
    int r = (int)(i & (R_ - 1));
    const float* g = gates + b * (4 * R_);
    float iv = sigm(g[r]);
    float fv = sigm(g[R_ + r]);
    float gv = tanhf(g[2 * R_ + r]);
    float ov = sigm(g[3 * R_ + r]);
    float c = fv * cprev[i] + iv * gv;
    float h = ov * tanhf(c);
    out_half[b * (2 * R_) + r] = h;
    nh[i] = h;
    nc[i] = c;
}

// ---------------- launch ----------------
extern "C" void kernel_launch(void* const* d_in, const int* in_sizes, int n_in,
                              void* d_out, int out_size)
{
    (void)in_sizes; (void)n_in; (void)out_size;
    const float* xt      = (const float*)d_in[0];
    const float* event   = (const float*)d_in[2];
    const float* clip    = (const float*)d_in[3];
    const int*   clip_mask = (const int*)d_in[4];
    const float* state_h = (const float*)d_in[5];
    const float* state_c = (const float*)d_in[6];
    const float* W_ih0   = (const float*)d_in[7];
    const float* b_ih0   = (const float*)d_in[8];
    const float* W_hh0   = (const float*)d_in[9];
    const float* b_hh0   = (const float*)d_in[10];
    const float* W_ih1   = (const float*)d_in[11];
    const float* b_ih1   = (const float*)d_in[12];
    const float* W_hh1   = (const float*)d_in[13];
    const float* b_hh1   = (const float*)d_in[14];
    const float* W_ctx   = (const float*)d_in[15];
    const float* b_ctx   = (const float*)d_in[16];
    const float* W_h2a   = (const float*)d_in[17];
    const float* b_h2a   = (const float*)d_in[18];
    const float* W_alpha = (const float*)d_in[19];

    float* out  = (float*)d_out;
    float* newh = out + (long)B_ * 2 * R_;
    float* newc = newh + 2L * B_ * R_;

    float *gates0, *gates1, *atth, *scores2, *wts, *attout;
    cudaGetSymbolAddress((void**)&gates0, g_gates0);
    cudaGetSymbolAddress((void**)&gates1, g_gates1);
    cudaGetSymbolAddress((void**)&atth,   g_atth);
    cudaGetSymbolAddress((void**)&scores2, g_scores2);
    cudaGetSymbolAddress((void**)&wts,    g_wts);
    cudaGetSymbolAddress((void**)&attout, g_attout);

    const float* h0 = state_h;
    const float* h1 = state_h + (long)B_ * R_;
    const float* c0 = state_c;
    const float* c1 = state_c + (long)B_ * R_;

    cudaFuncSetAttribute(gemm_f16x2, cudaFuncAttributeMaxDynamicSharedMemorySize, 2 * GBUF);
    cudaFuncSetAttribute(att_f16,    cudaFuncAttributeMaxDynamicSharedMemorySize, 2 * ABUF);

    // 1) gates0 = [xt|event|h0] @ [W_ih0|W_hh0]^T + b_ih0 + b_hh0
    gemm_f16x2<<<dim3(16, 8), 512, 2 * GBUF>>>(xt, event, h0, W_ih0, W_hh0, 2048, 1024, 3072,
                                               b_ih0, b_hh0, gates0, 4096);
    // 2) atth = h1 @ W_h2a^T + b_h2a + b_ctx
    gemm_f16x2<<<dim3(2, 8), 512, 2 * GBUF>>>(h1, h1, h1, W_h2a, W_h2a, 1024, 1024, 1024,
                                              b_h2a, b_ctx, atth, 512);
    // 3) fused attention scores (fp16), 2 H-partials
    att_f16<<<dim3(2, 512), 512, 2 * ABUF>>>(clip, W_ctx, atth, W_alpha, scores2);
    // 4) masked softmax (b_alpha shift-invariant)
    softmax_kernel<<<B_, 32>>>(scores2, clip_mask, wts);
    // 5) attout = weights @ clip
    attsum_kernel<<<B_, 256>>>(clip, wts, attout);
    // 6) gates1 = [xt|attout|h1] @ [W_ih1|W_hh1]^T + b_ih1 + b_hh1
    gemm_f16x2<<<dim3(16, 8), 512, 2 * GBUF>>>(xt, attout, h1, W_ih1, W_hh1, 2048, 1024, 3072,
                                               b_ih1, b_hh1, gates1, 4096);
    // 7) LSTM pointwise
    {
        int threads = 256;
        int blocks = (int)(((long)B_ * R_ + threads - 1) / threads);
        lstm_act<<<blocks, threads>>>(gates0, c0, out,      newh,                 newc);
        lstm_act<<<blocks, threads>>>(gates1, c1, out + R_, newh + (long)B_ * R_, newc + (long)B_ * R_);
    }
}